// round 2
// baseline (speedup 1.0000x reference)
#include <cuda_runtime.h>
#include <cuda_bf16.h>
#include <cstdint>

#define BIGV 10000000000.0f
#define F_L2E 1.4426950408889634f
#define F_LN2 0.6931471805599453f

// D in anti-diagonal-major layout: g_D[b][k][i] = D[b][i][j] with k = i + j
// (0-based i,j in [0,512), k in [0,1023)). Dims [64][1024][512] = 134 MB.
__device__ float g_D[(size_t)64 * 1024 * 512];

__device__ __forceinline__ float ex2f_(float x) {
    float r; asm("ex2.approx.f32 %0, %1;" : "=f"(r) : "f"(x)); return r;
}
__device__ __forceinline__ float lg2f_(float x) {
    float r; asm("lg2.approx.f32 %0, %1;" : "=f"(r) : "f"(x)); return r;
}

// ---------------------------------------------------------------------------
// Kernel 1: squared distances, written anti-diagonal-major.
// Grid (8, 8, 64): one 64x64 (i,j) tile per block, 256 threads, 4x4 microtile.
// ---------------------------------------------------------------------------
__global__ __launch_bounds__(256) void sqdist_kernel(const float* __restrict__ x,
                                                     const float* __restrict__ y)
{
    __shared__ __align__(16) float xs[16][64];   // [d][i]
    __shared__ __align__(16) float ys[16][64];   // [d][j]
    __shared__ float x2s[64], y2s[64];
    __shared__ float ts[64][66];                 // [ii][jj], padded

    const int b   = blockIdx.z;
    const int i0  = blockIdx.y * 64;
    const int j0  = blockIdx.x * 64;
    const int tid = threadIdx.x;

    // Load 64x16 tiles of x and y (coalesced float4), store transposed.
    {
        int row = tid >> 2;
        int d0  = (tid & 3) * 4;
        float4 xv = *(const float4*)(x + ((size_t)(b * 512 + i0 + row)) * 16 + d0);
        xs[d0 + 0][row] = xv.x; xs[d0 + 1][row] = xv.y;
        xs[d0 + 2][row] = xv.z; xs[d0 + 3][row] = xv.w;
        float4 yv = *(const float4*)(y + ((size_t)(b * 512 + j0 + row)) * 16 + d0);
        ys[d0 + 0][row] = yv.x; ys[d0 + 1][row] = yv.y;
        ys[d0 + 2][row] = yv.z; ys[d0 + 3][row] = yv.w;
    }
    __syncthreads();

    if (tid < 64) {
        float s = 0.f;
        #pragma unroll
        for (int d = 0; d < 16; d++) s += xs[d][tid] * xs[d][tid];
        x2s[tid] = s;
    } else if (tid < 128) {
        int c = tid - 64;
        float s = 0.f;
        #pragma unroll
        for (int d = 0; d < 16; d++) s += ys[d][c] * ys[d][c];
        y2s[c] = s;
    }
    __syncthreads();

    const int tx = tid & 15;          // 16 threads over j
    const int ty = tid >> 4;          // 16 threads over i
    float acc[4][4];
    #pragma unroll
    for (int r = 0; r < 4; r++)
        #pragma unroll
        for (int c = 0; c < 4; c++) acc[r][c] = 0.f;

    #pragma unroll
    for (int d = 0; d < 16; d++) {
        float4 av = *(const float4*)&xs[d][ty * 4];
        float4 bv = *(const float4*)&ys[d][tx * 4];
        float a[4]  = {av.x, av.y, av.z, av.w};
        float bb[4] = {bv.x, bv.y, bv.z, bv.w};
        #pragma unroll
        for (int r = 0; r < 4; r++)
            #pragma unroll
            for (int c = 0; c < 4; c++) acc[r][c] = fmaf(a[r], bb[c], acc[r][c]);
    }

    #pragma unroll
    for (int r = 0; r < 4; r++) {
        float xv2 = x2s[ty * 4 + r];
        #pragma unroll
        for (int c = 0; c < 4; c++)
            ts[ty * 4 + r][tx * 4 + c] = fmaf(-2.f, acc[r][c], xv2 + y2s[tx * 4 + c]);
    }
    __syncthreads();

    // Scatter to anti-diagonal-major: g_D[b][i0+j0+kk][i0+ii], jj = kk-ii in [0,64)
    const size_t bbase = ((size_t)b) << 19;   // b * 1024 * 512
    for (int idx = tid; idx < 127 * 64; idx += 256) {
        int kk = idx >> 6;
        int ii = idx & 63;
        int jj = kk - ii;
        if ((unsigned)jj < 64u)
            g_D[bbase + ((size_t)(i0 + j0 + kk) << 9) + (size_t)(i0 + ii)] = ts[ii][jj];
    }
}

// ---------------------------------------------------------------------------
// Kernel 2: soft-DTW wavefront. One block per batch, 512 threads.
// Thread tid owns row i = tid+1 (1-based). Wavefront over k = i+j, k=2..1024.
// Registers: rP1 = R[i][j-1] (value at step k-1), rP2 = R[i][j-2] (step k-2).
// Cross-warp boundary (row 32w) via double-buffered smem, 1 barrier/step.
// ---------------------------------------------------------------------------
__global__ __launch_bounds__(512) void dtw_kernel(float* __restrict__ out)
{
    const int b    = blockIdx.x;
    const int tid  = threadIdx.x;
    const int lane = tid & 31;
    const int w    = tid >> 5;
    const int i    = tid + 1;

    __shared__ float s1[2][18];   // [parity][warp]: row 32w value at step k-1
    __shared__ float s2[2][18];   // [parity][warp]: row 32w value at step k-2

    if (tid < 36)      ((float*)s1)[tid]      = BIGV;
    else if (tid < 72) ((float*)s2)[tid - 36] = BIGV;
    __syncthreads();

    const size_t bbase = ((size_t)b) << 19;

    float rP1 = BIGV, rP2 = BIGV;   // R[i][j-1], R[i][j-2]

    // Prefetch ring: dbuf[(k-2)&3] holds D for diagonal k.
    float dbuf[4];
    #pragma unroll
    for (int t = 0; t < 4; t++)
        dbuf[t] = g_D[bbase + ((size_t)t << 9) + (size_t)tid];

    #pragma unroll 4
    for (int k = 2; k <= 1024; ++k) {
        const int p = k & 1;
        float d = dbuf[(k - 2) & 3];
        // Prefetch diagonal k+4 into the slot just consumed.
        {
            int kk = k + 4; if (kk > 1024) kk = 1024;
            dbuf[(k - 2) & 3] = g_D[bbase + ((size_t)(kk - 2) << 9) + (size_t)tid];
        }

        float up   = __shfl_up_sync(0xffffffffu, rP1, 1);   // R[i-1][j]
        float diag = __shfl_up_sync(0xffffffffu, rP2, 1);   // R[i-1][j-1]
        if (lane == 0) {
            if (w == 0) { up = BIGV; diag = (k == 2) ? 0.0f : BIGV; }
            else        { up = s1[p][w]; diag = s2[p][w]; }
        }
        float left = rP1;                                   // R[i][j-1]

        // softmin = -ln(e^-a + e^-b + e^-c), gamma = 1, via median-of-3
        float mn1 = fminf(diag, up), mx1 = fmaxf(diag, up);
        float mn  = fminf(mn1, left);
        float mid = fmaxf(mn1, fminf(mx1, left));
        float mx  = fmaxf(mx1, left);
        float t2  = ex2f_((mn - mid) * F_L2E) + ex2f_((mn - mx) * F_L2E);
        float smin = mn - F_LN2 * lg2f_(1.0f + t2);

        int j = k - i;
        float rNew = (j >= 1 && j <= 512) ? (d + smin) : BIGV;

        rP2 = rP1;
        rP1 = rNew;

        if (lane == 31) {            // feed warp w+1's boundary, next parity
            s1[p ^ 1][w + 1] = rP1;
            s2[p ^ 1][w + 1] = rP2;
        }
        __syncthreads();
    }

    if (tid == 511) out[b] = rP1;    // R[512][512]
}

extern "C" void kernel_launch(void* const* d_in, const int* in_sizes, int n_in,
                              void* d_out, int out_size)
{
    const float* x = (const float*)d_in[0];
    const float* y = (const float*)d_in[1];
    float* out = (float*)d_out;

    dim3 g1(8, 8, 64);
    sqdist_kernel<<<g1, 256>>>(x, y);
    dtw_kernel<<<64, 512>>>(out);
}

// round 3
// speedup vs baseline: 1.2997x; 1.2997x over previous
#include <cuda_runtime.h>
#include <cuda_bf16.h>
#include <cstdint>

#define BIGV 10000000000.0f
#define F_L2E 1.4426950408889634f
#define F_LN2 0.6931471805599453f

// D (pre-scaled by log2(e)) in anti-diagonal-major layout:
// g_D[b][kd][i0] = log2e * D[b][i0][j0] with kd = i0 + j0 (0-based), dims [64][1024][512].
__device__ float g_D[(size_t)64 * 1024 * 512];

__device__ __forceinline__ float ex2f_(float x) {
    float r; asm("ex2.approx.f32 %0, %1;" : "=f"(r) : "f"(x)); return r;
}
__device__ __forceinline__ float lg2f_(float x) {
    float r; asm("lg2.approx.f32 %0, %1;" : "=f"(r) : "f"(x)); return r;
}
__device__ __forceinline__ void st_release_shared(int* p, int v) {
    unsigned a = (unsigned)__cvta_generic_to_shared(p);
    asm volatile("st.release.cta.shared.b32 [%0], %1;" :: "r"(a), "r"(v) : "memory");
}
__device__ __forceinline__ int ld_acquire_shared(const int* p) {
    unsigned a = (unsigned)__cvta_generic_to_shared(p);
    int v; asm volatile("ld.acquire.cta.shared.b32 %0, [%1];" : "=r"(v) : "r"(a) : "memory");
    return v;
}

// ---------------------------------------------------------------------------
// Kernel 1: squared distances * log2e, written anti-diagonal-major.
// Grid (8, 8, 64): one 64x64 (i,j) tile per block, 256 threads, 4x4 microtile.
// ---------------------------------------------------------------------------
__global__ __launch_bounds__(256) void sqdist_kernel(const float* __restrict__ x,
                                                     const float* __restrict__ y)
{
    __shared__ __align__(16) float xs[16][64];   // [d][i]
    __shared__ __align__(16) float ys[16][64];   // [d][j]
    __shared__ float x2s[64], y2s[64];
    __shared__ float ts[64][66];                 // [ii][jj], padded

    const int b   = blockIdx.z;
    const int i0  = blockIdx.y * 64;
    const int j0  = blockIdx.x * 64;
    const int tid = threadIdx.x;

    {
        int row = tid >> 2;
        int d0  = (tid & 3) * 4;
        float4 xv = *(const float4*)(x + ((size_t)(b * 512 + i0 + row)) * 16 + d0);
        xs[d0 + 0][row] = xv.x; xs[d0 + 1][row] = xv.y;
        xs[d0 + 2][row] = xv.z; xs[d0 + 3][row] = xv.w;
        float4 yv = *(const float4*)(y + ((size_t)(b * 512 + j0 + row)) * 16 + d0);
        ys[d0 + 0][row] = yv.x; ys[d0 + 1][row] = yv.y;
        ys[d0 + 2][row] = yv.z; ys[d0 + 3][row] = yv.w;
    }
    __syncthreads();

    if (tid < 64) {
        float s = 0.f;
        #pragma unroll
        for (int d = 0; d < 16; d++) s += xs[d][tid] * xs[d][tid];
        x2s[tid] = s;
    } else if (tid < 128) {
        int c = tid - 64;
        float s = 0.f;
        #pragma unroll
        for (int d = 0; d < 16; d++) s += ys[d][c] * ys[d][c];
        y2s[c] = s;
    }
    __syncthreads();

    const int tx = tid & 15;
    const int ty = tid >> 4;
    float acc[4][4];
    #pragma unroll
    for (int r = 0; r < 4; r++)
        #pragma unroll
        for (int c = 0; c < 4; c++) acc[r][c] = 0.f;

    #pragma unroll
    for (int d = 0; d < 16; d++) {
        float4 av = *(const float4*)&xs[d][ty * 4];
        float4 bv = *(const float4*)&ys[d][tx * 4];
        float a[4]  = {av.x, av.y, av.z, av.w};
        float bb[4] = {bv.x, bv.y, bv.z, bv.w};
        #pragma unroll
        for (int r = 0; r < 4; r++)
            #pragma unroll
            for (int c = 0; c < 4; c++) acc[r][c] = fmaf(a[r], bb[c], acc[r][c]);
    }

    #pragma unroll
    for (int r = 0; r < 4; r++) {
        float xv2 = x2s[ty * 4 + r];
        #pragma unroll
        for (int c = 0; c < 4; c++)
            ts[ty * 4 + r][tx * 4 + c] = fmaf(-2.f, acc[r][c], xv2 + y2s[tx * 4 + c]);
    }
    __syncthreads();

    const size_t bbase = ((size_t)b) << 19;   // b * 1024 * 512
    for (int idx = tid; idx < 127 * 64; idx += 256) {
        int kk = idx >> 6;
        int ii = idx & 63;
        int jj = kk - ii;
        if ((unsigned)jj < 64u)
            g_D[bbase + ((size_t)(i0 + j0 + kk) << 9) + (size_t)(i0 + ii)]
                = ts[ii][jj] * F_L2E;
    }
}

// ---------------------------------------------------------------------------
// Kernel 2: soft-DTW wavefront, warp-skewed (NO block barriers in main loop).
// One block per batch, 512 threads = 16 warps; warp w owns rows 32w+1..32w+32
// (1-based). Warp w iterates only its active window k in [32w+2, 32w+545]
// (543 real steps + 1 pad step for 8-chunk alignment).
// Cross-warp boundary: warp w's last row (i=32w+32) values, one per step,
// stored write-once into ring[w][0..511]; progress published per 8-step chunk
// with st.release, consumed with an ld.acquire spin.
// All values carry an implicit log2(e) scale factor (D pre-scaled); softmin is
// smin' = mn' - lg2(1 + 2^(mn'-mid') + 2^(mn'-mx')), exact logsumexp.
// ---------------------------------------------------------------------------
__global__ __launch_bounds__(512) void dtw_kernel(float* __restrict__ out)
{
    __shared__ float ring[16][516];
    __shared__ int prog[16];

    const int b    = blockIdx.x;
    const int tid  = threadIdx.x;
    const int lane = tid & 31;
    const int w    = tid >> 5;
    const int offW = w << 5;
    const int i    = tid + 1;          // 1-based row

    if (tid < 16) prog[tid] = 0;
    __syncthreads();                    // once; main loop is barrier-free

    const float* Dp       = g_D + (((size_t)b) << 19) + (size_t)tid;  // + row (i-1)
    const float* ringPrev = ring[(w > 0) ? (w - 1) : 0];
    float*       ringMy   = ring[w];

    const int kbeg    = offW + 2;
    const int kend_pf = offW + 545;     // prefetch clamp (pad step inclusive)

    float rP1 = BIGV, rP2 = BIGV;       // R[i] at steps k-1, k-2

    float dbuf[8];
    #pragma unroll
    for (int s = 0; s < 8; ++s)
        dbuf[s] = Dp[(size_t)(kbeg + s - 2) << 9];

    int j = kbeg - i;                   // j = k - i at first step

    #pragma unroll 1
    for (int c = 0; c < 68; ++c) {
        const int k0 = kbeg + (c << 3);

        if (w > 0) {                    // wait for producer warp's chunk
            int need = (c << 3) + 8; if (need > 512) need = 512;
            while (ld_acquire_shared(&prog[w - 1]) < need) { }
        }

        #pragma unroll
        for (int s = 0; s < 8; ++s) {
            const int k = k0 + s;
            float d = dbuf[s];
            int kp = k + 8; if (kp > kend_pf) kp = kend_pf;
            dbuf[s] = Dp[(size_t)(kp - 2) << 9];

            float up = __shfl_up_sync(0xffffffffu, rP1, 1);   // R[i-1][j]
            float dg = __shfl_up_sync(0xffffffffu, rP2, 1);   // R[i-1][j-1]

            // Boundary (lane 0): row 32w values from producer's ring.
            // ring[w-1][t] = row 32w at step k' = 32w+1+t, t in [0,511].
            int tu  = k - offW - 2;                 // index for step k-1
            int iu  = (tu < 511) ? tu : 511;
            int idg = tu - 1; if (idg < 0) idg = 0; if (idg > 511) idg = 511;
            float bu = ringPrev[iu];                // broadcast LDS
            float bd = ringPrev[idg];
            float upB = (tu <= 511)            ? bu : BIGV;
            float dgB = (tu >= 1 && tu <= 512) ? bd : BIGV;
            if (w == 0) { upB = BIGV; dgB = (k == 2) ? 0.0f : BIGV; }
            if (lane == 0) { up = upB; dg = dgB; }

            float left = rP1;                       // R[i][j-1]
            float mn1 = fminf(dg, up),  mx1 = fmaxf(dg, up);
            float mn  = fminf(mn1, left);
            float mid = fmaxf(mn1, fminf(mx1, left));
            float mx  = fmaxf(mx1, left);
            float t2  = ex2f_(mn - mid) + ex2f_(mn - mx);
            float l2  = lg2f_(1.0f + t2);
            float rNew = (d + mn) - l2;
            rNew = ((unsigned)(j - 1) < 512u) ? rNew : BIGV;

            rP2 = rP1; rP1 = rNew;
            ++j;

            // ring[w][t] = my last row (i = 32w+32) at step k, t = k-32w-33.
            int t = k - offW - 33;
            if (lane == 31 && (unsigned)t <= 511u) ringMy[t] = rNew;
        }

        // publish progress once per chunk: entries up to t = 8c-24 are written
        {
            int pub = (c << 3) - 23;
            if (pub > 512) pub = 512;
            if (lane == 31 && pub > 0) st_release_shared(&prog[w], pub);
        }
    }

    // After the pad step, rP2 = value at k = offW+544; thread 511: R[512][512].
    if (tid == 511) out[b] = rP2 * F_LN2;   // undo log2e scaling
}

extern "C" void kernel_launch(void* const* d_in, const int* in_sizes, int n_in,
                              void* d_out, int out_size)
{
    const float* x = (const float*)d_in[0];
    const float* y = (const float*)d_in[1];
    float* out = (float*)d_out;

    dim3 g1(8, 8, 64);
    sqdist_kernel<<<g1, 256>>>(x, y);
    dtw_kernel<<<64, 512>>>(out);
}

// round 4
// speedup vs baseline: 1.8770x; 1.4443x over previous
#include <cuda_runtime.h>
#include <cuda_bf16.h>
#include <cstdint>

#define BIGV 10000000000.0f
#define F_L2E 1.4426950408889634f
#define F_LN2 0.6931471805599453f

// D (pre-scaled by log2(e)) in anti-diagonal-major layout:
// g_D[b][kd][i0] = log2e * D[b][i0][j0], kd = i0 + j0 (0-based), dims [64][1024][512].
__device__ float g_D[(size_t)64 * 1024 * 512];

__device__ __forceinline__ float ex2f_(float x) {
    float r; asm("ex2.approx.f32 %0, %1;" : "=f"(r) : "f"(x)); return r;
}
__device__ __forceinline__ float lg2f_(float x) {
    float r; asm("lg2.approx.f32 %0, %1;" : "=f"(r) : "f"(x)); return r;
}
__device__ __forceinline__ void st_release_shared(int* p, int v) {
    unsigned a = (unsigned)__cvta_generic_to_shared(p);
    asm volatile("st.release.cta.shared.b32 [%0], %1;" :: "r"(a), "r"(v) : "memory");
}
__device__ __forceinline__ int ld_acquire_shared(const int* p) {
    unsigned a = (unsigned)__cvta_generic_to_shared(p);
    int v; asm volatile("ld.acquire.cta.shared.b32 %0, [%1];" : "=r"(v) : "r"(a) : "memory");
    return v;
}

// ---------------------------------------------------------------------------
// Kernel 1: squared distances * log2e, written anti-diagonal-major.
// ---------------------------------------------------------------------------
__global__ __launch_bounds__(256) void sqdist_kernel(const float* __restrict__ x,
                                                     const float* __restrict__ y)
{
    __shared__ __align__(16) float xs[16][64];
    __shared__ __align__(16) float ys[16][64];
    __shared__ float x2s[64], y2s[64];
    __shared__ float ts[64][66];

    const int b   = blockIdx.z;
    const int i0  = blockIdx.y * 64;
    const int j0  = blockIdx.x * 64;
    const int tid = threadIdx.x;

    {
        int row = tid >> 2;
        int d0  = (tid & 3) * 4;
        float4 xv = *(const float4*)(x + ((size_t)(b * 512 + i0 + row)) * 16 + d0);
        xs[d0 + 0][row] = xv.x; xs[d0 + 1][row] = xv.y;
        xs[d0 + 2][row] = xv.z; xs[d0 + 3][row] = xv.w;
        float4 yv = *(const float4*)(y + ((size_t)(b * 512 + j0 + row)) * 16 + d0);
        ys[d0 + 0][row] = yv.x; ys[d0 + 1][row] = yv.y;
        ys[d0 + 2][row] = yv.z; ys[d0 + 3][row] = yv.w;
    }
    __syncthreads();

    if (tid < 64) {
        float s = 0.f;
        #pragma unroll
        for (int d = 0; d < 16; d++) s += xs[d][tid] * xs[d][tid];
        x2s[tid] = s;
    } else if (tid < 128) {
        int c = tid - 64;
        float s = 0.f;
        #pragma unroll
        for (int d = 0; d < 16; d++) s += ys[d][c] * ys[d][c];
        y2s[c] = s;
    }
    __syncthreads();

    const int tx = tid & 15;
    const int ty = tid >> 4;
    float acc[4][4];
    #pragma unroll
    for (int r = 0; r < 4; r++)
        #pragma unroll
        for (int c = 0; c < 4; c++) acc[r][c] = 0.f;

    #pragma unroll
    for (int d = 0; d < 16; d++) {
        float4 av = *(const float4*)&xs[d][ty * 4];
        float4 bv = *(const float4*)&ys[d][tx * 4];
        float a[4]  = {av.x, av.y, av.z, av.w};
        float bb[4] = {bv.x, bv.y, bv.z, bv.w};
        #pragma unroll
        for (int r = 0; r < 4; r++)
            #pragma unroll
            for (int c = 0; c < 4; c++) acc[r][c] = fmaf(a[r], bb[c], acc[r][c]);
    }

    #pragma unroll
    for (int r = 0; r < 4; r++) {
        float xv2 = x2s[ty * 4 + r];
        #pragma unroll
        for (int c = 0; c < 4; c++)
            ts[ty * 4 + r][tx * 4 + c] = fmaf(-2.f, acc[r][c], xv2 + y2s[tx * 4 + c]);
    }
    __syncthreads();

    const size_t bbase = ((size_t)b) << 19;
    for (int idx = tid; idx < 127 * 64; idx += 256) {
        int kk = idx >> 6;
        int ii = idx & 63;
        int jj = kk - ii;
        if ((unsigned)jj < 64u)
            g_D[bbase + ((size_t)(i0 + j0 + kk) << 9) + (size_t)(i0 + ii)]
                = ts[ii][jj] * F_L2E;
    }
}

// ---------------------------------------------------------------------------
// Kernel 2: soft-DTW wavefront, warp-skewed, slim 3-phase inner loop.
// One block per batch, 512 threads = 16 warps; warp w owns rows 32w+1..32w+32.
// Step q = 0..543 maps to diagonal k = 32w+2+q. One shfl + one LDS per step:
// dg(k) = up(k-1), bd(k) = bu(k-1). Cross-warp boundary in ring[w+1], progress
// published per 8-step chunk (st.release / ld.acquire).
// Values carry an implicit log2(e) factor; softmin via 2x ex2 + 1x lg2.
// ---------------------------------------------------------------------------
__global__ __launch_bounds__(512) void dtw_kernel(float* __restrict__ out)
{
    __shared__ float ring[17][516];
    __shared__ int prog[17];

    const int b    = blockIdx.x;
    const int tid  = threadIdx.x;
    const int lane = tid & 31;
    const int w    = tid >> 5;
    const int offW = w << 5;

    for (int idx = tid; idx < 516; idx += 512) ring[0][idx] = BIGV;
    if (tid < 17) prog[tid] = (tid == 0) ? 512 : 0;
    __syncthreads();

    const float* __restrict__ dp0   = g_D + (((size_t)b) << 19) + (size_t)tid;
    const float* __restrict__ ringR = ring[w];
    float*       __restrict__ ringW = ring[w + 1];
    const int kbeg = offW + 2;
    const int kIdxMax = offW + 543;       // max (k-2) index ever touched

    float rP1 = BIGV, rP2 = BIGV;
    float up_prev = BIGV;
    float bu_prev = (w == 0) ? 0.0f : BIGV;

    float dcur[8], dnx[8];
    #pragma unroll
    for (int s = 0; s < 8; ++s) dcur[s] = dp0[(size_t)(kbeg - 2 + s) << 9];

#define DTW_STEP(SIDX, Q, TU, DOVALID, VPRED, STORECHK) do {                   \
        float d_   = dcur[SIDX];                                               \
        float upv_ = __shfl_up_sync(0xffffffffu, rP1, 1);                      \
        float bu_  = ringR[(TU)];                                              \
        float dgv_ = (lane == 0) ? bu_prev : up_prev;                          \
        float upm_ = (lane == 0) ? bu_ : upv_;                                 \
        up_prev = upv_; bu_prev = bu_;                                         \
        float mn1_ = fminf(dgv_, upm_), mx1_ = fmaxf(dgv_, upm_);              \
        float mn_  = fminf(mn1_, rP1);                                         \
        float mid_ = fmaxf(mn1_, fminf(mx1_, rP1));                            \
        float mx_  = fmaxf(mx1_, rP1);                                         \
        float t2_  = ex2f_(mn_ - mid_) + ex2f_(mn_ - mx_);                     \
        float sm_  = lg2f_(1.0f + t2_);                                        \
        float rN_  = d_ + mn_ - sm_;                                           \
        if (DOVALID) rN_ = (VPRED) ? rN_ : BIGV;                               \
        rP2 = rP1; rP1 = rN_;                                                  \
        int tS_ = (Q) - 31;                                                    \
        if (lane == 31 && (!(STORECHK) || tS_ >= 0)) ringW[tS_] = rN_;         \
    } while (0)

    // ---- ramp-in: chunks 0..3 (q = 0..31) ----
    #pragma unroll 1
    for (int c = 0; c < 4; ++c) {
        if (w) {
            int need = 8 * c + 8;
            if (ld_acquire_shared(&prog[w]) < need)
                while (ld_acquire_shared(&prog[w]) < need) __nanosleep(64);
        }
        int kn = kbeg + 8 * (c + 1) - 2;
        #pragma unroll
        for (int s = 0; s < 8; ++s) dnx[s] = dp0[(size_t)(kn + s) << 9];
        #pragma unroll
        for (int s = 0; s < 8; ++s) {
            int q = 8 * c + s;
            DTW_STEP(s, q, q, true, lane <= q, true);
        }
        #pragma unroll
        for (int s = 0; s < 8; ++s) dcur[s] = dnx[s];
        int pub = 8 * c - 23;
        if (lane == 31 && pub > 0) st_release_shared(&prog[w + 1], pub);
    }

    // ---- steady: chunks 4..63 (q = 32..511), all lanes valid ----
    #pragma unroll 1
    for (int c = 4; c < 64; ++c) {
        if (w) {
            int need = 8 * c + 8;
            if (ld_acquire_shared(&prog[w]) < need)
                while (ld_acquire_shared(&prog[w]) < need) __nanosleep(64);
        }
        int kn = kbeg + 8 * (c + 1) - 2;
        #pragma unroll
        for (int s = 0; s < 8; ++s) dnx[s] = dp0[(size_t)(kn + s) << 9];
        #pragma unroll
        for (int s = 0; s < 8; ++s) {
            int q = 8 * c + s;
            DTW_STEP(s, q, q, false, true, false);
        }
        #pragma unroll
        for (int s = 0; s < 8; ++s) dcur[s] = dnx[s];
        int pub = 8 * c - 23;
        if (lane == 31) st_release_shared(&prog[w + 1], pub);
    }

    // ---- ramp-out: chunks 64..67 (q = 512..543); lane 0 never valid -> no waits ----
    #pragma unroll 1
    for (int c = 64; c < 68; ++c) {
        int kn = kbeg + 8 * (c + 1) - 2;
        #pragma unroll
        for (int s = 0; s < 8; ++s) {
            int kk = kn + s; if (kk > kIdxMax) kk = kIdxMax;
            dnx[s] = dp0[(size_t)kk << 9];
        }
        #pragma unroll
        for (int s = 0; s < 8; ++s) {
            int q  = 8 * c + s;
            int tu = q < 511 ? q : 511;
            DTW_STEP(s, q, tu, true, lane >= q - 511, false);
        }
        #pragma unroll
        for (int s = 0; s < 8; ++s) dcur[s] = dnx[s];
        int pub = 8 * c - 23; if (pub > 512) pub = 512;
        if (lane == 31) st_release_shared(&prog[w + 1], pub);
    }
#undef DTW_STEP

    // Last step q=543 is the pad step; rP2 = value at q=542 = R[512][512] (tid 511).
    if (tid == 511) out[b] = rP2 * F_LN2;
}

extern "C" void kernel_launch(void* const* d_in, const int* in_sizes, int n_in,
                              void* d_out, int out_size)
{
    const float* x = (const float*)d_in[0];
    const float* y = (const float*)d_in[1];
    float* out = (float*)d_out;

    dim3 g1(8, 8, 64);
    sqdist_kernel<<<g1, 256>>>(x, y);
    dtw_kernel<<<64, 512>>>(out);
}